// round 2
// baseline (speedup 1.0000x reference)
#include <cuda_runtime.h>
#include <cuda_bf16.h>
#include <cstdint>

// Problem constants
#define K_STATES 64
#define D_DIM    512
#define BATCH    512
#define T_FULL   128
#define T_STEPS  126            // real word positions 1..126
#define P_TOTAL  (BATCH * T_STEPS)   // 64512
#define BOS_TAG  63
#define EOS_TAG  62

// Scratch: emission logits L[p][k] = ThetaB[k] . E[words[p]]
__device__ float g_L[(size_t)P_TOTAL * K_STATES];   // 16.5 MB

static __device__ __forceinline__ uint32_t pack_bf16x2(float x, float y) {
    __nv_bfloat162 p = __floats2bfloat162_rn(x, y);
    uint32_t u;
    memcpy(&u, &p, 4);
    return u;
}

// ---------------------------------------------------------------------------
// Kernel 1: gathered GEMM  L[p][k] = sum_d E[word_p][d] * ThetaB[k][d]
// bf16 mma.sync m16n8k16, fp32 accumulate. CTA tile: 64 positions x 64 states.
// ---------------------------------------------------------------------------
#define PTILE     64
#define CHUNK     64
#define S_STRIDE  72   // bf16 elems per shared row (64 + 8 pad)

__global__ __launch_bounds__(128) void emit_gemm_kernel(
    const float* __restrict__ ThetaB,
    const float* __restrict__ E,
    const int*   __restrict__ words)
{
    __shared__ __nv_bfloat16 Es [PTILE    * S_STRIDE];
    __shared__ __nv_bfloat16 Ths[K_STATES * S_STRIDE];
    __shared__ int sWord[PTILE];

    const int tid    = threadIdx.x;
    const int p_base = blockIdx.x * PTILE;

    if (tid < PTILE) {
        int p = p_base + tid;
        int b = p / T_STEPS;
        int t = p - b * T_STEPS;
        sWord[tid] = words[b * T_FULL + t + 1];
    }
    __syncthreads();

    const int lane = tid & 31;
    const int warp = tid >> 5;
    const int g    = lane >> 2;   // groupID
    const int tig  = lane & 3;    // threadID_in_group
    const int wrow = warp * 16;   // warp's row offset within the 64-pos tile

    float c[8][4];
    #pragma unroll
    for (int nt = 0; nt < 8; nt++)
        #pragma unroll
        for (int i = 0; i < 4; i++) c[nt][i] = 0.f;

    for (int ch = 0; ch < D_DIM / CHUNK; ch++) {
        const int doff = ch * CHUNK;

        // Stage E rows (gathered, fp32 -> bf16)
        #pragma unroll
        for (int i = 0; i < 8; i++) {
            int flat = tid + 128 * i;          // 0..1023
            int row  = flat >> 4;
            int seg  = flat & 15;
            float4 v = *(const float4*)&E[(size_t)sWord[row] * D_DIM + doff + seg * 4];
            uint32_t* dst = (uint32_t*)&Es[row * S_STRIDE + seg * 4];
            dst[0] = pack_bf16x2(v.x, v.y);
            dst[1] = pack_bf16x2(v.z, v.w);
        }
        // Stage ThetaB (fp32 -> bf16)
        #pragma unroll
        for (int i = 0; i < 8; i++) {
            int flat = tid + 128 * i;
            int row  = flat >> 4;
            int seg  = flat & 15;
            float4 v = *(const float4*)&ThetaB[row * D_DIM + doff + seg * 4];
            uint32_t* dst = (uint32_t*)&Ths[row * S_STRIDE + seg * 4];
            dst[0] = pack_bf16x2(v.x, v.y);
            dst[1] = pack_bf16x2(v.z, v.w);
        }
        __syncthreads();

        #pragma unroll
        for (int ks = 0; ks < 4; ks++) {
            const int kof = ks * 16;
            uint32_t a0 = *(const uint32_t*)&Es[(wrow + g    ) * S_STRIDE + kof + 2 * tig    ];
            uint32_t a1 = *(const uint32_t*)&Es[(wrow + g + 8) * S_STRIDE + kof + 2 * tig    ];
            uint32_t a2 = *(const uint32_t*)&Es[(wrow + g    ) * S_STRIDE + kof + 2 * tig + 8];
            uint32_t a3 = *(const uint32_t*)&Es[(wrow + g + 8) * S_STRIDE + kof + 2 * tig + 8];
            #pragma unroll
            for (int nt = 0; nt < 8; nt++) {
                uint32_t b0 = *(const uint32_t*)&Ths[(nt * 8 + g) * S_STRIDE + kof + 2 * tig    ];
                uint32_t b1 = *(const uint32_t*)&Ths[(nt * 8 + g) * S_STRIDE + kof + 2 * tig + 8];
                asm volatile(
                    "mma.sync.aligned.m16n8k16.row.col.f32.bf16.bf16.f32 "
                    "{%0,%1,%2,%3}, {%4,%5,%6,%7}, {%8,%9}, {%0,%1,%2,%3};"
                    : "+f"(c[nt][0]), "+f"(c[nt][1]), "+f"(c[nt][2]), "+f"(c[nt][3])
                    : "r"(a0), "r"(a1), "r"(a2), "r"(a3), "r"(b0), "r"(b1));
            }
        }
        __syncthreads();
    }

    // Store C tile: rows wrow+g / wrow+g+8, cols nt*8 + 2tig (+1)
    #pragma unroll
    for (int nt = 0; nt < 8; nt++) {
        int col  = nt * 8 + 2 * tig;
        size_t r0 = (size_t)(p_base + wrow + g) * K_STATES + col;
        size_t r1 = (size_t)(p_base + wrow + g + 8) * K_STATES + col;
        *(float2*)&g_L[r0] = make_float2(c[nt][0], c[nt][1]);
        *(float2*)&g_L[r1] = make_float2(c[nt][2], c[nt][3]);
    }
}

// ---------------------------------------------------------------------------
// Kernel 2: forward recursion (unsup) + closed-form tagged score.
// 1 warp per sequence, 4 sequences per CTA, 2 states per lane.
// A = exp(WA) in shared (row j contiguous -> conflict-free float2 reads).
// ---------------------------------------------------------------------------
#define SEQ_PER_CTA 4

__global__ __launch_bounds__(32 * SEQ_PER_CTA) void forward_kernel(
    const float* __restrict__ WA,
    const int*   __restrict__ tags,
    float*       __restrict__ out)
{
    __shared__ float A_sh[K_STATES * K_STATES];   // 16 KB
    __shared__ float alpha_sh[SEQ_PER_CTA][K_STATES];

    const int tid  = threadIdx.x;
    const int lane = tid & 31;
    const int w    = tid >> 5;

    // Build A = exp(WA), column BOS forbidden. 128 threads cover 2 cells/row.
    for (int i = 0; i < K_STATES; i += 2) {
        int row = i + (tid >> 6);       // tid 0-63 -> row i, 64-127 -> row i+1
        int col = tid & 63;
        float v = (col == BOS_TAG) ? 0.f : __expf(WA[row * K_STATES + col]);
        A_sh[row * K_STATES + col] = v;
    }
    __syncthreads();

    const int seq = blockIdx.x * SEQ_PER_CTA + w;
    const float* Lbase = &g_L[(size_t)seq * T_STEPS * K_STATES];

    // alpha: lane holds states 2l, 2l+1. Init one-hot at BOS (state 63).
    float ax = 0.f, ay = (lane == 31) ? 1.f : 0.f;
    float logsum = 0.f;

    for (int t = 0; t < T_STEPS; t++) {
        *(float2*)&alpha_sh[w][2 * lane] = make_float2(ax, ay);
        __syncwarp();

        float2 s0 = {0.f, 0.f}, s1 = {0.f, 0.f}, s2 = {0.f, 0.f}, s3 = {0.f, 0.f};
        #pragma unroll
        for (int j = 0; j < K_STATES; j += 4) {
            float a0 = alpha_sh[w][j];
            float a1 = alpha_sh[w][j + 1];
            float a2 = alpha_sh[w][j + 2];
            float a3 = alpha_sh[w][j + 3];
            float2 r0 = *(const float2*)&A_sh[(j    ) * K_STATES + 2 * lane];
            float2 r1 = *(const float2*)&A_sh[(j + 1) * K_STATES + 2 * lane];
            float2 r2 = *(const float2*)&A_sh[(j + 2) * K_STATES + 2 * lane];
            float2 r3 = *(const float2*)&A_sh[(j + 3) * K_STATES + 2 * lane];
            s0.x = fmaf(a0, r0.x, s0.x); s0.y = fmaf(a0, r0.y, s0.y);
            s1.x = fmaf(a1, r1.x, s1.x); s1.y = fmaf(a1, r1.y, s1.y);
            s2.x = fmaf(a2, r2.x, s2.x); s2.y = fmaf(a2, r2.y, s2.y);
            s3.x = fmaf(a3, r3.x, s3.x); s3.y = fmaf(a3, r3.y, s3.y);
        }
        __syncwarp();
        float sx = (s0.x + s1.x) + (s2.x + s3.x);
        float sy = (s0.y + s1.y) + (s2.y + s3.y);

        // emission (states 62/63 have clamped ~0 emission in the reference)
        float2 Lv = *(const float2*)&Lbase[t * K_STATES + 2 * lane];
        float ex = __expf(Lv.x), ey = __expf(Lv.y);
        if (lane == 31) { ex = 0.f; ey = 0.f; }
        sx *= ex; sy *= ey;

        // rescale by max of alpha
        float m = fmaxf(sx, sy);
        #pragma unroll
        for (int off = 16; off; off >>= 1)
            m = fmaxf(m, __shfl_xor_sync(0xffffffffu, m, off));
        logsum += logf(m);
        float inv = 1.0f / m;
        ax = sx * inv; ay = sy * inv;
    }

    // val = alpha . A[:, EOS]
    float pv = ax * A_sh[(2 * lane) * K_STATES + EOS_TAG]
             + ay * A_sh[(2 * lane + 1) * K_STATES + EOS_TAG];
    #pragma unroll
    for (int off = 16; off; off >>= 1)
        pv += __shfl_xor_sync(0xffffffffu, pv, off);
    float unsup = logf(pv) + logsum;

    // Tagged score: closed form (one-hot support makes alpha rank-1 each step)
    const int* tg = &tags[seq * T_FULL];
    float tsum = 0.f;
    for (int p = 1 + lane; p <= T_STEPS; p += 32) {
        int cur  = tg[p];
        int prev = (p == 1) ? BOS_TAG : tg[p - 1];
        tsum += WA[prev * K_STATES + cur] + Lbase[(size_t)(p - 1) * K_STATES + cur];
    }
    #pragma unroll
    for (int off = 16; off; off >>= 1)
        tsum += __shfl_xor_sync(0xffffffffu, tsum, off);

    if (lane == 0) {
        tsum += WA[tg[T_STEPS] * K_STATES + EOS_TAG];
        out[seq] = tsum - unsup;
    }
}

// ---------------------------------------------------------------------------
extern "C" void kernel_launch(void* const* d_in, const int* in_sizes, int n_in,
                              void* d_out, int out_size)
{
    const float* WA     = (const float*)d_in[0];
    const float* ThetaB = (const float*)d_in[1];
    const float* E      = (const float*)d_in[2];
    const int*   words  = (const int*)  d_in[3];
    const int*   tags   = (const int*)  d_in[4];
    float*       out    = (float*)d_out;

    emit_gemm_kernel<<<P_TOTAL / PTILE, 128>>>(ThetaB, E, words);
    forward_kernel<<<BATCH / SEQ_PER_CTA, 32 * SEQ_PER_CTA>>>(WA, tags, out);
}

// round 4
// speedup vs baseline: 2.1639x; 2.1639x over previous
#include <cuda_runtime.h>
#include <cuda_bf16.h>
#include <cstdint>
#include <cstring>

// Problem constants
#define K_STATES 64
#define D_DIM    512
#define BATCH    512
#define T_FULL   128
#define T_STEPS  126            // real word positions 1..126
#define P_TOTAL  (BATCH * T_STEPS)   // 64512
#define BOS_TAG  63
#define EOS_TAG  62

// Scratch: emission logits L[p][k] = ThetaB[k] . E[words[p]]
__device__ float g_L[(size_t)P_TOTAL * K_STATES];   // 16.5 MB

static __device__ __forceinline__ uint32_t pack_bf16x2(float x, float y) {
    __nv_bfloat162 p = __floats2bfloat162_rn(x, y);
    uint32_t u;
    memcpy(&u, &p, 4);
    return u;
}

// ---------------------------------------------------------------------------
// Kernel 1: gathered GEMM  L[p][k] = sum_d E[word_p][d] * ThetaB[k][d]
// bf16 mma.sync m16n8k16, fp32 accumulate. CTA tile: 64 positions x 64 states.
// E rows (DRAM-gather) are register-prefetched one chunk ahead.
// ---------------------------------------------------------------------------
#define PTILE     64
#define CHUNK     64
#define S_STRIDE  72   // bf16 elems per shared row (64 + 8 pad)

__global__ __launch_bounds__(128) void emit_gemm_kernel(
    const float* __restrict__ ThetaB,
    const float* __restrict__ E,
    const int*   __restrict__ words)
{
    __shared__ __nv_bfloat16 Es [PTILE    * S_STRIDE];
    __shared__ __nv_bfloat16 Ths[K_STATES * S_STRIDE];
    __shared__ int sWord[PTILE];

    const int tid    = threadIdx.x;
    const int p_base = blockIdx.x * PTILE;

    if (tid < PTILE) {
        int p = p_base + tid;
        int b = p / T_STEPS;
        int t = p - b * T_STEPS;
        sWord[tid] = words[b * T_FULL + t + 1];
    }
    __syncthreads();

    const int lane = tid & 31;
    const int warp = tid >> 5;
    const int g    = lane >> 2;   // groupID
    const int tig  = lane & 3;    // threadID_in_group
    const int wrow = warp * 16;   // warp's row offset within the 64-pos tile

    float c[8][4];
    #pragma unroll
    for (int nt = 0; nt < 8; nt++)
        #pragma unroll
        for (int i = 0; i < 4; i++) c[nt][i] = 0.f;

    // Prefetch E chunk 0 into registers
    float4 ev[8];
    #pragma unroll
    for (int i = 0; i < 8; i++) {
        int flat = tid + 128 * i;
        int row  = flat >> 4;
        int seg  = flat & 15;
        ev[i] = *(const float4*)&E[(size_t)sWord[row] * D_DIM + seg * 4];
    }

    for (int ch = 0; ch < D_DIM / CHUNK; ch++) {
        const int doff = ch * CHUNK;

        // Stage E from prefetch registers (fp32 -> bf16)
        #pragma unroll
        for (int i = 0; i < 8; i++) {
            int flat = tid + 128 * i;
            int row  = flat >> 4;
            int seg  = flat & 15;
            uint32_t* dst = (uint32_t*)&Es[row * S_STRIDE + seg * 4];
            dst[0] = pack_bf16x2(ev[i].x, ev[i].y);
            dst[1] = pack_bf16x2(ev[i].z, ev[i].w);
        }
        // Stage ThetaB directly (L2-resident, fp32 -> bf16)
        #pragma unroll
        for (int i = 0; i < 8; i++) {
            int flat = tid + 128 * i;
            int row  = flat >> 4;
            int seg  = flat & 15;
            float4 v = *(const float4*)&ThetaB[row * D_DIM + doff + seg * 4];
            uint32_t* dst = (uint32_t*)&Ths[row * S_STRIDE + seg * 4];
            dst[0] = pack_bf16x2(v.x, v.y);
            dst[1] = pack_bf16x2(v.z, v.w);
        }
        __syncthreads();

        // Issue next chunk's E gather now; it overlaps the mma loop below.
        if (ch + 1 < D_DIM / CHUNK) {
            #pragma unroll
            for (int i = 0; i < 8; i++) {
                int flat = tid + 128 * i;
                int row  = flat >> 4;
                int seg  = flat & 15;
                ev[i] = *(const float4*)&E[(size_t)sWord[row] * D_DIM + doff + CHUNK + seg * 4];
            }
        }

        #pragma unroll
        for (int ks = 0; ks < 4; ks++) {
            const int kof = ks * 16;
            uint32_t a0 = *(const uint32_t*)&Es[(wrow + g    ) * S_STRIDE + kof + 2 * tig    ];
            uint32_t a1 = *(const uint32_t*)&Es[(wrow + g + 8) * S_STRIDE + kof + 2 * tig    ];
            uint32_t a2 = *(const uint32_t*)&Es[(wrow + g    ) * S_STRIDE + kof + 2 * tig + 8];
            uint32_t a3 = *(const uint32_t*)&Es[(wrow + g + 8) * S_STRIDE + kof + 2 * tig + 8];
            #pragma unroll
            for (int nt = 0; nt < 8; nt++) {
                uint32_t b0 = *(const uint32_t*)&Ths[(nt * 8 + g) * S_STRIDE + kof + 2 * tig    ];
                uint32_t b1 = *(const uint32_t*)&Ths[(nt * 8 + g) * S_STRIDE + kof + 2 * tig + 8];
                asm volatile(
                    "mma.sync.aligned.m16n8k16.row.col.f32.bf16.bf16.f32 "
                    "{%0,%1,%2,%3}, {%4,%5,%6,%7}, {%8,%9}, {%0,%1,%2,%3};"
                    : "+f"(c[nt][0]), "+f"(c[nt][1]), "+f"(c[nt][2]), "+f"(c[nt][3])
                    : "r"(a0), "r"(a1), "r"(a2), "r"(a3), "r"(b0), "r"(b1));
            }
        }
        __syncthreads();
    }

    // Store C tile
    #pragma unroll
    for (int nt = 0; nt < 8; nt++) {
        int col  = nt * 8 + 2 * tig;
        size_t r0 = (size_t)(p_base + wrow + g) * K_STATES + col;
        size_t r1 = (size_t)(p_base + wrow + g + 8) * K_STATES + col;
        *(float2*)&g_L[r0] = make_float2(c[nt][0], c[nt][1]);
        *(float2*)&g_L[r1] = make_float2(c[nt][2], c[nt][3]);
    }
}

// ---------------------------------------------------------------------------
// Kernel 2: forward recursion, one CTA (64 threads = 2 warps) per sequence.
// Thread c owns output state c and keeps A column c in 64 registers.
// Per step: 16 broadcast LDS.128 of alpha + 64 register FMAs.
// Rescale (max + log) only every 8 steps.
// ---------------------------------------------------------------------------
__global__ __launch_bounds__(64) void forward_kernel(
    const float* __restrict__ WA,
    const int*   __restrict__ tags,
    float*       __restrict__ out)
{
    __shared__ __align__(16) float abuf[2][K_STATES];
    __shared__ float red[2];

    const int c    = threadIdx.x;       // state / column 0..63
    const int lane = c & 31;
    const int w    = c >> 5;
    const int seq  = blockIdx.x;

    // A column c in registers: Acol[j] = exp(WA[j][c]); column BOS forbidden.
    float Acol[K_STATES];
    #pragma unroll
    for (int j = 0; j < K_STATES; j++) {
        float v = __expf(WA[j * K_STATES + c]);
        Acol[j] = (c == BOS_TAG) ? 0.f : v;
    }

    const float* Lseq = &g_L[(size_t)seq * T_STEPS * K_STATES];

    abuf[0][c] = (c == BOS_TAG) ? 1.f : 0.f;
    __syncthreads();

    // Rolling emission prefetch (2 steps ahead)
    float Lcur  = Lseq[c];
    float Lnext = Lseq[K_STATES + c];

    float logsum = 0.f;
    float s = 0.f;

    for (int t = 0; t < T_STEPS; t++) {
        const float4* ab = (const float4*)abuf[t & 1];
        float a0 = 0.f, a1 = 0.f, a2 = 0.f, a3 = 0.f;
        #pragma unroll
        for (int q = 0; q < 16; q++) {
            float4 av = ab[q];
            a0 = fmaf(av.x, Acol[4 * q    ], a0);
            a1 = fmaf(av.y, Acol[4 * q + 1], a1);
            a2 = fmaf(av.z, Acol[4 * q + 2], a2);
            a3 = fmaf(av.w, Acol[4 * q + 3], a3);
        }
        s = (a0 + a1) + (a2 + a3);

        float e = __expf(Lcur);
        if (c >= EOS_TAG) e = 0.f;      // EOS/BOS emissions clamped ~0
        s *= e;

        Lcur = Lnext;
        if (t + 2 < T_STEPS) Lnext = Lseq[(size_t)(t + 2) * K_STATES + c];

        if ((t & 7) == 7) {
            // periodic rescale: m = max over 64 threads
            float m = s;
            #pragma unroll
            for (int off = 16; off; off >>= 1)
                m = fmaxf(m, __shfl_xor_sync(0xffffffffu, m, off));
            if (lane == 0) red[w] = m;
            __syncthreads();
            m = fmaxf(red[0], red[1]);
            logsum += __logf(m);
            s = __fdividef(s, m);
        }

        abuf[(t + 1) & 1][c] = s;
        __syncthreads();
    }

    // val = alpha . A[:, EOS]; thread c contributes alpha_c * A[c][EOS]
    float pv = s * __expf(WA[c * K_STATES + EOS_TAG]);
    #pragma unroll
    for (int off = 16; off; off >>= 1)
        pv += __shfl_xor_sync(0xffffffffu, pv, off);
    if (lane == 0) red[w] = pv;
    __syncthreads();
    float unsup = __logf(red[0] + red[1]) + logsum;
    __syncthreads();

    // Tagged score: closed form (one-hot support makes alpha rank-1 each step)
    const int* tg = &tags[seq * T_FULL];
    float tsum = 0.f;
    for (int p = 1 + c; p <= T_STEPS; p += K_STATES) {
        int cur  = tg[p];
        int prev = (p == 1) ? BOS_TAG : tg[p - 1];
        tsum += WA[prev * K_STATES + cur] + Lseq[(size_t)(p - 1) * K_STATES + cur];
    }
    #pragma unroll
    for (int off = 16; off; off >>= 1)
        tsum += __shfl_xor_sync(0xffffffffu, tsum, off);
    if (lane == 0) red[w] = tsum;
    __syncthreads();

    if (c == 0) {
        float tagged = red[0] + red[1] + WA[tg[T_STEPS] * K_STATES + EOS_TAG];
        out[seq] = tagged - unsup;
    }
}

// ---------------------------------------------------------------------------
extern "C" void kernel_launch(void* const* d_in, const int* in_sizes, int n_in,
                              void* d_out, int out_size)
{
    const float* WA     = (const float*)d_in[0];
    const float* ThetaB = (const float*)d_in[1];
    const float* E      = (const float*)d_in[2];
    const int*   words  = (const int*)  d_in[3];
    const int*   tags   = (const int*)  d_in[4];
    float*       out    = (float*)d_out;

    emit_gemm_kernel<<<P_TOTAL / PTILE, 128>>>(ThetaB, E, words);
    forward_kernel<<<BATCH, 64>>>(WA, tags, out);
}